// round 5
// baseline (speedup 1.0000x reference)
#include <cuda_runtime.h>

#define S 2048
#define DM 512
#define NI 13
#define NC 117

typedef unsigned long long ull;

// ---------------- scratch ----------------
__device__ float  g_Wp[DM * 128];            // padded W, [k][128]
__device__ float4 g_plin[NI * S];            // {x0, y0, cw, sw} lin channel, [i][a]
__device__ float4 g_pang[NI * S];            // ang channel
__device__ float  g_base[NI * S];            // min + noise_bias, [i][b]
__device__ float  g_partial[10 * NI * S];    // slots 0..7: 256-a-chunks, 8: diag, 9: odd full128

// ---------------- packed f32x2 helpers ----------------
__device__ __forceinline__ ull pk2(float lo, float hi) {
    ull r; asm("mov.b64 %0, {%1,%2};" : "=l"(r) : "f"(lo), "f"(hi)); return r;
}
__device__ __forceinline__ void upk2(ull v, float& lo, float& hi) {
    asm("mov.b64 {%0,%1}, %2;" : "=f"(lo), "=f"(hi) : "l"(v));
}
__device__ __forceinline__ ull fma2(ull a, ull b, ull c) {
    ull d; asm("fma.rn.f32x2 %0, %1, %2, %3;" : "=l"(d) : "l"(a), "l"(b), "l"(c)); return d;
}
__device__ __forceinline__ ull mul2(ull a, ull b) {
    ull d; asm("mul.rn.f32x2 %0, %1, %2;" : "=l"(d) : "l"(a), "l"(b)); return d;
}
__device__ __forceinline__ ull add2(ull a, ull b) {
    ull d; asm("add.rn.f32x2 %0, %1, %2;" : "=l"(d) : "l"(a), "l"(b)); return d;
}
__device__ __forceinline__ ull neg2(ull a) { return a ^ 0x8000000080000000ULL; }

__device__ __forceinline__ float softplus_f(float x) {
    return fmaxf(x, 0.0f) + log1pf(expf(-fabsf(x)));
}

// packed complex pow: (rx,ry) = (bx,by)^e, 11-bit exponent
__device__ __forceinline__ void cpow2(ull bx, ull by, unsigned e, ull& rx, ull& ry) {
    rx = pk2(1.0f, 1.0f); ry = pk2(0.0f, 0.0f);
    #pragma unroll
    for (int it = 0; it < 11; it++) {
        if (e & 1u) {
            ull t = fma2(rx, bx, neg2(mul2(ry, by)));
            ry = fma2(rx, by, mul2(ry, bx));
            rx = t;
        }
        e >>= 1;
        ull t2 = mul2(bx, by);
        bx = fma2(bx, bx, neg2(mul2(by, by)));
        by = add2(t2, t2);
    }
}

// ---------------- 0) pad W ----------------
__global__ void wprep_kernel(const float* __restrict__ W) {
    int idx = blockIdx.x * 256 + threadIdx.x;   // DM*128 = 65536
    int k = idx >> 7, c = idx & 127;
    g_Wp[idx] = (c < NC) ? W[k * NC + c] : 0.0f;
}

// ---------------- 1) fused LN + GEMM + param transform ----------------
// 128 blocks x 128 threads; block = 16 tokens x 128 cols over K=512.
__global__ __launch_bounds__(128) void gemm_fused(
    const float* __restrict__ h, const float* __restrict__ mn,
    const float* __restrict__ lw, const float* __restrict__ lb,
    const float* __restrict__ bias)
{
    __shared__ float xs[16][512];   // 32 KB, reused for p in epilogue

    int t  = threadIdx.x;
    int s0 = blockIdx.x * 16;

    // ---- LayerNorm: 8 threads per row, 16 rows ----
    {
        int r = t >> 3, sub = t & 7;
        const float4* h4 = (const float4*)h;
        float4 v[16];
        float sum = 0.f, sq = 0.f;
        #pragma unroll
        for (int q = 0; q < 16; q++) {
            v[q] = h4[(s0 + r) * (DM / 4) + sub + q * 8];
            sum += v[q].x + v[q].y + v[q].z + v[q].w;
            sq  += v[q].x * v[q].x + v[q].y * v[q].y + v[q].z * v[q].z + v[q].w * v[q].w;
        }
        #pragma unroll
        for (int o = 4; o; o >>= 1) {
            sum += __shfl_xor_sync(0xffffffffu, sum, o);
            sq  += __shfl_xor_sync(0xffffffffu, sq,  o);
        }
        float mu   = sum * (1.0f / DM);
        float var  = sq * (1.0f / DM) - mu * mu;
        float rstd = rsqrtf(var + 1e-5f);
        const float4* lw4 = (const float4*)lw;
        const float4* lb4 = (const float4*)lb;
        #pragma unroll
        for (int q = 0; q < 16; q++) {
            float4 wv = lw4[sub + q * 8], bv = lb4[sub + q * 8], o4;
            o4.x = (v[q].x - mu) * rstd * wv.x + bv.x;
            o4.y = (v[q].y - mu) * rstd * wv.y + bv.y;
            o4.z = (v[q].z - mu) * rstd * wv.z + bv.z;
            o4.w = (v[q].w - mu) * rstd * wv.w + bv.w;
            ((float4*)xs[r])[sub + q * 8] = o4;
        }
    }
    __syncthreads();

    // ---- GEMM: thread = tokens {tp, tp+8} x cols [tc*8, tc*8+8) ----
    int tc = t & 15, tp = t >> 4;
    ull A[4], B[4];
    #pragma unroll
    for (int q = 0; q < 4; q++) { A[q] = pk2(0.f, 0.f); B[q] = A[q]; }

    const float4* Wp4 = (const float4*)g_Wp;
    #pragma unroll 8
    for (int k = 0; k < DM; k++) {
        float xa = xs[tp][k];
        float xb = xs[tp + 8][k];
        float4 w0 = Wp4[k * 32 + tc * 2];
        float4 w1 = Wp4[k * 32 + tc * 2 + 1];
        ull xa2 = pk2(xa, xa), xb2 = pk2(xb, xb);
        ull wp0 = pk2(w0.x, w0.y), wp1 = pk2(w0.z, w0.w);
        ull wp2 = pk2(w1.x, w1.y), wp3 = pk2(w1.z, w1.w);
        A[0] = fma2(xa2, wp0, A[0]);  A[1] = fma2(xa2, wp1, A[1]);
        A[2] = fma2(xa2, wp2, A[2]);  A[3] = fma2(xa2, wp3, A[3]);
        B[0] = fma2(xb2, wp0, B[0]);  B[1] = fma2(xb2, wp1, B[1]);
        B[2] = fma2(xb2, wp2, B[2]);  B[3] = fma2(xb2, wp3, B[3]);
    }
    __syncthreads();

    // ---- epilogue: p -> smem (reuse xs as ps[16][128]) ----
    float* ps = &xs[0][0];
    {
        int c0 = tc * 8;
        #pragma unroll
        for (int q = 0; q < 4; q++) {
            float a0, a1, b0v, b1v;
            upk2(A[q], a0, a1); upk2(B[q], b0v, b1v);
            int c = c0 + q * 2;
            float bb0 = (c + 0 < NC) ? bias[c + 0] : 0.0f;
            float bb1 = (c + 1 < NC) ? bias[c + 1] : 0.0f;
            ps[tp * 128 + c + 0] = a0 + bb0;
            ps[tp * 128 + c + 1] = a1 + bb1;
            ps[(tp + 8) * 128 + c + 0] = b0v + bb0;
            ps[(tp + 8) * 128 + c + 1] = b1v + bb1;
        }
    }
    __syncthreads();

    // ---- param transform: 16 tokens x 13 imus = 208 units ----
    for (int u = t; u < 16 * NI; u += 128) {
        int r = u / NI, i = u % NI;
        int s = s0 + r;
        const float* P = ps + r * 128;
        float p0   = P[0 * NI + i];
        float p1   = P[1 * NI + i];
        float p2   = P[2 * NI + i];
        float p3   = P[3 * NI + i];
        float c    = P[4 * NI + i];
        float c_th = P[5 * NI + i];
        float phi  = P[6 * NI + i];
        float phth = P[7 * NI + i];
        float p8   = P[8 * NI + i];
        {
            float d  = sqrtf(p1 * p1 + 1e-5f);
            float sp = softplus_f(p0);
            float k  = d * d * 0.25f + sp;
            float om = 0.5f * sqrtf(fmaxf(4.0f * k - d * d, 0.0f));
            float dec = expf(-0.5f * d);
            float so, co; sincosf(om, &so, &co);
            float sp_, cp_; sincosf(phi, &sp_, &cp_);
            g_plin[i * S + s] = make_float4(c * cp_, c * sp_, dec * co, dec * so);
        }
        {
            float d  = sqrtf(p3 * p3 + 1e-5f);
            float sp = softplus_f(p2);
            float k  = d * d * 0.25f + sp;
            float om = 0.5f * sqrtf(fmaxf(4.0f * k - d * d, 0.0f));
            float dec = expf(-0.5f * d);
            float so, co; sincosf(om, &so, &co);
            float sp_, cp_; sincosf(phth, &sp_, &cp_);
            g_pang[i * S + s] = make_float4(c_th * cp_, c_th * sp_, dec * co, dec * so);
        }
        g_base[i * S + s] = mn[0] + p8;
    }
}

// ---------------- 2) triangular sweep ----------------
// smem lane buffer: [bb][lane] stride 33 -> conflict-free STS and LDS.
#define SB_STRIDE 33

__device__ __forceinline__ void fold_sbuf(const float* sbuf, float* pout, int lane) {
    #pragma unroll
    for (int g4 = 0; g4 < 4; g4++) {
        int bb = g4 * 32 + lane;
        const float* row = sbuf + bb * SB_STRIDE;
        float acc = 0.0f;
        #pragma unroll
        for (int c = 0; c < 32; c++) acc += row[c];
        pout[bb] = acc;
    }
}

// NJ a-groups of 32, fully-past tile (all a < b0): binexp init, no birth predicate
template<int NJ>
__device__ __forceinline__ void run_full(int a0, int b0, int i, float* pout,
                                         int lane, float* sbuf) {
    ull X[NJ], Y[NJ], CW[NJ], SW[NJ], NSW[NJ];
    #pragma unroll
    for (int j = 0; j < NJ; j++) {
        int a = a0 + j * 32 + lane;
        float4 pl = g_plin[i * S + a];
        float4 pa = g_pang[i * S + a];
        CW[j]  = pk2(pl.z, pa.z);
        SW[j]  = pk2(pl.w, pa.w);
        NSW[j] = neg2(SW[j]);
        ull rx, ry;
        cpow2(CW[j], SW[j], (unsigned)(b0 - a), rx, ry);
        ull x0 = pk2(pl.x, pa.x), y0 = pk2(pl.y, pa.y);
        X[j] = fma2(x0, rx, neg2(mul2(y0, ry)));
        Y[j] = fma2(x0, ry, mul2(y0, rx));
    }
    #pragma unroll 4
    for (int bb = 0; bb < 128; bb++) {
        ull s2 = Y[0];
        #pragma unroll
        for (int j = 1; j < NJ; j++) s2 = add2(s2, Y[j]);
        float slo, shi; upk2(s2, slo, shi);
        sbuf[bb * SB_STRIDE + lane] = slo + shi;
        #pragma unroll
        for (int j = 0; j < NJ; j++) {
            ull t1 = mul2(Y[j], NSW[j]);
            ull t2 = mul2(X[j], SW[j]);
            X[j] = fma2(X[j], CW[j], t1);
            Y[j] = fma2(Y[j], CW[j], t2);
        }
    }
    __syncwarp();
    fold_sbuf(sbuf, pout, lane);
}

__device__ __forceinline__ void run_diag(int b0, int i, float* pout,
                                         int lane, float* sbuf) {
    ull X[4], Y[4], X0[4], Y0[4], CW[4], SW[4], NSW[4];
    int aj[4];
    #pragma unroll
    for (int j = 0; j < 4; j++) {
        int a = b0 + j * 32 + lane;
        aj[j] = a;
        float4 pl = g_plin[i * S + a];
        float4 pa = g_pang[i * S + a];
        CW[j]  = pk2(pl.z, pa.z);
        SW[j]  = pk2(pl.w, pa.w);
        NSW[j] = neg2(SW[j]);
        X0[j] = pk2(pl.x, pa.x);
        Y0[j] = pk2(pl.y, pa.y);
        X[j] = pk2(0.f, 0.f); Y[j] = X[j];
    }
    #pragma unroll 4
    for (int bb = 0; bb < 128; bb++) {
        int b = b0 + bb;
        #pragma unroll
        for (int j = 0; j < 4; j++)
            if (b == aj[j]) { X[j] = X0[j]; Y[j] = Y0[j]; }
        ull s2 = add2(add2(Y[0], Y[1]), add2(Y[2], Y[3]));
        float slo, shi; upk2(s2, slo, shi);
        sbuf[bb * SB_STRIDE + lane] = slo + shi;
        #pragma unroll
        for (int j = 0; j < 4; j++) {
            ull t1 = mul2(Y[j], NSW[j]);
            ull t2 = mul2(X[j], SW[j]);
            X[j] = fma2(X[j], CW[j], t1);
            Y[j] = fma2(Y[j], CW[j], t2);
        }
    }
    __syncwarp();
    fold_sbuf(sbuf, pout, lane);
}

// slots 0..55: full256 (cb=2..15, ca=0..cb/2-1) -> partial slot ca
// slots 56..71: diag128 (cb = slot-56)          -> partial slot 8
// slots 72..79: full128 (cb = 2*(slot-72)+1, a-chunk cb-1) -> partial slot 9
__global__ __launch_bounds__(32) void sweep_kernel() {
    __shared__ float sbuf[128 * SB_STRIDE];
    int slot = blockIdx.x, i = blockIdx.y;
    int lane = threadIdx.x;
    if (slot < 56) {
        int s = slot, cb = 2;
        for (; cb < 16; cb++) { int m = cb >> 1; if (s < m) break; s -= m; }
        int ca = s;
        float* pout = g_partial + (ca * NI + i) * S + cb * 128;
        run_full<8>(ca * 256, cb * 128, i, pout, lane, sbuf);
    } else if (slot < 72) {
        int cb = slot - 56;
        float* pout = g_partial + (8 * NI + i) * S + cb * 128;
        run_diag(cb * 128, i, pout, lane, sbuf);
    } else {
        int cb = 2 * (slot - 72) + 1;
        float* pout = g_partial + (9 * NI + i) * S + cb * 128;
        run_full<4>((cb - 1) * 128, cb * 128, i, pout, lane, sbuf);
    }
}

// ---------------- 3) fold partials + base -> out ----------------
__global__ void reduce_kernel(float* __restrict__ out) {
    int idx = blockIdx.x * 256 + threadIdx.x;   // layout [i][b]
    if (idx >= NI * S) return;
    int i = idx / S;
    int b = idx % S;
    int cb = b >> 7;
    int m = cb >> 1;
    float s = g_base[idx] + g_partial[(8 * NI + i) * S + b];
    if (cb & 1) s += g_partial[(9 * NI + i) * S + b];
    for (int ca = 0; ca < m; ca++)
        s += g_partial[(ca * NI + i) * S + b];
    out[idx] = s;
}

// ---------------- launch ----------------
extern "C" void kernel_launch(void* const* d_in, const int* in_sizes, int n_in,
                              void* d_out, int out_size) {
    const float* h    = (const float*)d_in[0];
    const float* mn   = (const float*)d_in[1];
    const float* lw   = (const float*)d_in[2];
    const float* lb   = (const float*)d_in[3];
    const float* W    = (const float*)d_in[4];
    const float* bias = (const float*)d_in[5];
    float* out = (float*)d_out;

    wprep_kernel<<<256, 256>>>(W);
    gemm_fused<<<S / 16, 128>>>(h, mn, lw, lb, bias);
    dim3 g(80, NI);
    sweep_kernel<<<g, 32>>>();
    reduce_kernel<<<(NI * S + 255) / 256, 256>>>(out);
}

// round 6
// speedup vs baseline: 1.1127x; 1.1127x over previous
#include <cuda_runtime.h>

#define S 2048
#define DM 512
#define NI 13
#define NC 117

typedef unsigned long long ull;

// ---------------- scratch ----------------
__device__ float  g_Wp[DM * 128];            // padded W, [k][128]
__device__ float4 g_plin[NI * S];            // {x0, y0, cw, sw} lin channel, [i][a]
__device__ float4 g_pang[NI * S];            // ang channel
__device__ float  g_base[NI * S];            // min + noise_bias, [i][b]
__device__ float  g_partial[16 * NI * S];    // [ca][i][b]

// ---------------- packed f32x2 helpers ----------------
__device__ __forceinline__ ull pk2(float lo, float hi) {
    ull r; asm("mov.b64 %0, {%1,%2};" : "=l"(r) : "f"(lo), "f"(hi)); return r;
}
__device__ __forceinline__ void upk2(ull v, float& lo, float& hi) {
    asm("mov.b64 {%0,%1}, %2;" : "=f"(lo), "=f"(hi) : "l"(v));
}
__device__ __forceinline__ ull fma2(ull a, ull b, ull c) {
    ull d; asm("fma.rn.f32x2 %0, %1, %2, %3;" : "=l"(d) : "l"(a), "l"(b), "l"(c)); return d;
}
__device__ __forceinline__ ull mul2(ull a, ull b) {
    ull d; asm("mul.rn.f32x2 %0, %1, %2;" : "=l"(d) : "l"(a), "l"(b)); return d;
}
__device__ __forceinline__ ull add2(ull a, ull b) {
    ull d; asm("add.rn.f32x2 %0, %1, %2;" : "=l"(d) : "l"(a), "l"(b)); return d;
}
__device__ __forceinline__ ull neg2(ull a) { return a ^ 0x8000000080000000ULL; }

__device__ __forceinline__ float softplus_f(float x) {
    return fmaxf(x, 0.0f) + log1pf(expf(-fabsf(x)));
}

// branchless packed complex pow: (rx,ry) = (bx,by)^e, e < 2048
__device__ __forceinline__ void cpow2(ull bx, ull by, unsigned e, ull& rx, ull& ry) {
    rx = pk2(1.0f, 1.0f); ry = pk2(0.0f, 0.0f);
    #pragma unroll
    for (int it = 0; it < 11; it++) {
        ull tx = fma2(rx, bx, neg2(mul2(ry, by)));
        ull ty = fma2(rx, by, mul2(ry, bx));
        bool m = (e & 1u) != 0u;
        rx = m ? tx : rx;
        ry = m ? ty : ry;
        e >>= 1;
        ull t2 = mul2(bx, by);
        bx = fma2(bx, bx, neg2(mul2(by, by)));
        by = add2(t2, t2);
    }
}

// ---------------- 0) pad W ----------------
__global__ void wprep_kernel(const float* __restrict__ W) {
    int idx = blockIdx.x * 256 + threadIdx.x;   // DM*128 = 65536
    int k = idx >> 7, c = idx & 127;
    g_Wp[idx] = (c < NC) ? W[k * NC + c] : 0.0f;
}

// ---------------- 1) fused LN + GEMM + param transform ----------------
// 128 blocks x 128 threads; block = 16 tokens. Token-pair f32x2 packing.
#define XROW 18
__global__ __launch_bounds__(128) void gemm_fused(
    const float* __restrict__ h, const float* __restrict__ mn,
    const float* __restrict__ lw, const float* __restrict__ lb,
    const float* __restrict__ bias)
{
    __shared__ __align__(16) float xsT[DM * XROW];   // [k][tok], padded row 18 -> 36.9 KB

    int t  = threadIdx.x;
    int s0 = blockIdx.x * 16;

    // ---- LayerNorm: 8 threads per row, 16 rows; store TRANSPOSED ----
    {
        int r = t >> 3, sub = t & 7;
        const float4* h4 = (const float4*)h;
        float4 v[16];
        float sum = 0.f, sq = 0.f;
        #pragma unroll
        for (int q = 0; q < 16; q++) {
            v[q] = h4[(s0 + r) * (DM / 4) + sub + q * 8];
            sum += v[q].x + v[q].y + v[q].z + v[q].w;
            sq  += v[q].x * v[q].x + v[q].y * v[q].y + v[q].z * v[q].z + v[q].w * v[q].w;
        }
        #pragma unroll
        for (int o = 4; o; o >>= 1) {
            sum += __shfl_xor_sync(0xffffffffu, sum, o);
            sq  += __shfl_xor_sync(0xffffffffu, sq,  o);
        }
        float mu   = sum * (1.0f / DM);
        float var  = sq * (1.0f / DM) - mu * mu;
        float rstd = rsqrtf(var + 1e-5f);
        const float4* lw4 = (const float4*)lw;
        const float4* lb4 = (const float4*)lb;
        #pragma unroll
        for (int q = 0; q < 16; q++) {
            float4 wv = lw4[sub + q * 8], bv = lb4[sub + q * 8];
            int k0 = (sub + q * 8) * 4;
            xsT[(k0 + 0) * XROW + r] = (v[q].x - mu) * rstd * wv.x + bv.x;
            xsT[(k0 + 1) * XROW + r] = (v[q].y - mu) * rstd * wv.y + bv.y;
            xsT[(k0 + 2) * XROW + r] = (v[q].z - mu) * rstd * wv.z + bv.z;
            xsT[(k0 + 3) * XROW + r] = (v[q].w - mu) * rstd * wv.w + bv.w;
        }
    }
    __syncthreads();

    // ---- GEMM: warp = 4 tokens (2 pairs), lane = 4 cols ----
    int lane = t & 31, w4 = (t >> 5) * 4;
    ull A[4], B[4];
    #pragma unroll
    for (int q = 0; q < 4; q++) { A[q] = pk2(0.f, 0.f); B[q] = A[q]; }

    const float4* Wp4 = (const float4*)g_Wp;
    #pragma unroll 4
    for (int k = 0; k < DM; k++) {
        ull x01 = *(const ull*)&xsT[k * XROW + w4];       // (tok0, tok1) broadcast
        ull x23 = *(const ull*)&xsT[k * XROW + w4 + 2];   // (tok2, tok3)
        float4 wv = Wp4[k * 32 + lane];
        ull wd0 = pk2(wv.x, wv.x), wd1 = pk2(wv.y, wv.y);
        ull wd2 = pk2(wv.z, wv.z), wd3 = pk2(wv.w, wv.w);
        A[0] = fma2(x01, wd0, A[0]);  A[1] = fma2(x01, wd1, A[1]);
        A[2] = fma2(x01, wd2, A[2]);  A[3] = fma2(x01, wd3, A[3]);
        B[0] = fma2(x23, wd0, B[0]);  B[1] = fma2(x23, wd1, B[1]);
        B[2] = fma2(x23, wd2, B[2]);  B[3] = fma2(x23, wd3, B[3]);
    }
    __syncthreads();

    // ---- epilogue: p -> smem (reuse xsT as ps[16][128]) ----
    float* ps = xsT;
    {
        int c0 = lane * 4;
        #pragma unroll
        for (int q = 0; q < 4; q++) {
            int c = c0 + q;
            float bb = (c < NC) ? bias[c] : 0.0f;
            float p0, p1, p2, p3;
            upk2(A[q], p0, p1); upk2(B[q], p2, p3);
            ps[(w4 + 0) * 128 + c] = p0 + bb;
            ps[(w4 + 1) * 128 + c] = p1 + bb;
            ps[(w4 + 2) * 128 + c] = p2 + bb;
            ps[(w4 + 3) * 128 + c] = p3 + bb;
        }
    }
    __syncthreads();

    // ---- param transform: 16 tokens x 13 imus x 2 channels = 416 units ----
    for (int u = t; u < 16 * NI * 2; u += 128) {
        int r   = u / (2 * NI);
        int rem = u - r * 2 * NI;
        int i = rem >> 1, ch = rem & 1;
        int s = s0 + r;
        const float* P = ps + r * 128;
        float pk  = P[(ch ? 2 : 0) * NI + i];
        float pd  = P[(ch ? 3 : 1) * NI + i];
        float pc  = P[(ch ? 5 : 4) * NI + i];
        float pph = P[(ch ? 7 : 6) * NI + i];

        float d  = sqrtf(pd * pd + 1e-5f);
        float sp = softplus_f(pk);
        float kk = d * d * 0.25f + sp;
        float om = 0.5f * sqrtf(fmaxf(4.0f * kk - d * d, 0.0f));
        float dec = expf(-0.5f * d);
        float so, co; sincosf(om, &so, &co);
        float sph, cph; sincosf(pph, &sph, &cph);
        float4 v = make_float4(pc * cph, pc * sph, dec * co, dec * so);
        if (ch) g_pang[i * S + s] = v;
        else    g_plin[i * S + s] = v;
        if (!ch) g_base[i * S + s] = mn[0] + P[8 * NI + i];
    }
}

// ---------------- 2) triangular sweep: uniform 128x128 tiles ----------------
template<bool DIAG>
__device__ __forceinline__ void run_tile(int a0, int b0, int i, float* pout,
                                         int lane, float* sbuf) {
    ull X[4], Y[4], CW[4], SW[4], NSW[4];
    ull X0[4], Y0[4];
    int aj[4];
    #pragma unroll
    for (int j = 0; j < 4; j++) {
        int a = a0 + j * 32 + lane;
        aj[j] = a;
        float4 pl = g_plin[i * S + a];
        float4 pa = g_pang[i * S + a];
        CW[j]  = pk2(pl.z, pa.z);
        SW[j]  = pk2(pl.w, pa.w);
        NSW[j] = neg2(SW[j]);
        ull x0 = pk2(pl.x, pa.x), y0 = pk2(pl.y, pa.y);
        if (DIAG) {
            X0[j] = x0; Y0[j] = y0;
            X[j] = pk2(0.f, 0.f); Y[j] = X[j];
        } else {
            ull rx, ry;
            cpow2(CW[j], SW[j], (unsigned)(b0 - a), rx, ry);
            X[j] = fma2(x0, rx, neg2(mul2(y0, ry)));
            Y[j] = fma2(x0, ry, mul2(y0, rx));
        }
    }
    #pragma unroll 4
    for (int bb = 0; bb < 128; bb++) {
        if (DIAG) {
            int b = b0 + bb;
            #pragma unroll
            for (int j = 0; j < 4; j++) {
                bool hit = (b == aj[j]);
                X[j] = hit ? X0[j] : X[j];
                Y[j] = hit ? Y0[j] : Y[j];
            }
        }
        ull s2 = add2(add2(Y[0], Y[1]), add2(Y[2], Y[3]));
        float slo, shi; upk2(s2, slo, shi);
        sbuf[bb * 32 + ((lane + bb) & 31)] = slo + shi;
        #pragma unroll
        for (int j = 0; j < 4; j++) {
            ull t1 = mul2(Y[j], NSW[j]);
            ull t2 = mul2(X[j], SW[j]);
            X[j] = fma2(X[j], CW[j], t1);
            Y[j] = fma2(Y[j], CW[j], t2);
        }
    }
    __syncwarp();
    #pragma unroll
    for (int g = 0; g < 4; g++) {
        int bb = g * 32 + lane;
        const float* row = sbuf + bb * 32;
        float acc = 0.0f;
        #pragma unroll
        for (int c = 0; c < 32; c++) acc += row[(bb + c) & 31];
        pout[bb] = acc;
    }
}

// grid (136, 13): slot -> (ca, cb) triangular, ca <= cb
__global__ __launch_bounds__(32) void sweep_kernel() {
    __shared__ float sbuf[128 * 32];   // 16 KB, rotation-indexed
    int slot = blockIdx.x, i = blockIdx.y;
    int lane = threadIdx.x;
    int s = slot, cb = 0;
    while (s > cb) { s -= (cb + 1); cb++; }
    int ca = s;
    float* pout = g_partial + (ca * NI + i) * S + cb * 128;
    if (ca == cb) run_tile<true >(ca * 128, cb * 128, i, pout, lane, sbuf);
    else          run_tile<false>(ca * 128, cb * 128, i, pout, lane, sbuf);
}

// ---------------- 3) fold partials + base -> out ----------------
__global__ void reduce_kernel(float* __restrict__ out) {
    int idx = blockIdx.x * 256 + threadIdx.x;   // layout [i][b]
    if (idx >= NI * S) return;
    int i = idx / S;
    int b = idx & (S - 1);
    int cb = b >> 7;
    float v[16];
    #pragma unroll
    for (int ca = 0; ca < 16; ca++)
        v[ca] = (ca <= cb) ? g_partial[(ca * NI + i) * S + b] : 0.0f;
    float s = g_base[idx];
    #pragma unroll
    for (int ca = 0; ca < 16; ca++) s += v[ca];
    out[idx] = s;
}

// ---------------- launch ----------------
extern "C" void kernel_launch(void* const* d_in, const int* in_sizes, int n_in,
                              void* d_out, int out_size) {
    const float* h    = (const float*)d_in[0];
    const float* mn   = (const float*)d_in[1];
    const float* lw   = (const float*)d_in[2];
    const float* lb   = (const float*)d_in[3];
    const float* W    = (const float*)d_in[4];
    const float* bias = (const float*)d_in[5];
    float* out = (float*)d_out;

    wprep_kernel<<<256, 256>>>(W);
    gemm_fused<<<S / 16, 128>>>(h, mn, lw, lb, bias);
    dim3 g(136, NI);
    sweep_kernel<<<g, 32>>>();
    reduce_kernel<<<(NI * S + 255) / 256, 256>>>(out);
}

// round 7
// speedup vs baseline: 1.4179x; 1.2742x over previous
#include <cuda_runtime.h>

#define S 2048
#define DM 512
#define NI 13
#define NC 117

typedef unsigned long long ull;

// ---------------- scratch ----------------
__device__ float  g_Wp[DM * 128];            // padded W, [k][128]
__device__ float4 g_plin[NI * S];            // {x0, y0, cw, sw} lin channel, [i][a]
__device__ float4 g_pang[NI * S];            // ang channel
__device__ float  g_base[NI * S];            // min + noise_bias, [i][b]
__device__ float  g_partial[16 * NI * S];    // [ca][i][b]

// ---------------- packed f32x2 helpers ----------------
__device__ __forceinline__ ull pk2(float lo, float hi) {
    ull r; asm("mov.b64 %0, {%1,%2};" : "=l"(r) : "f"(lo), "f"(hi)); return r;
}
__device__ __forceinline__ void upk2(ull v, float& lo, float& hi) {
    asm("mov.b64 {%0,%1}, %2;" : "=f"(lo), "=f"(hi) : "l"(v));
}
__device__ __forceinline__ ull fma2(ull a, ull b, ull c) {
    ull d; asm("fma.rn.f32x2 %0, %1, %2, %3;" : "=l"(d) : "l"(a), "l"(b), "l"(c)); return d;
}
__device__ __forceinline__ ull mul2(ull a, ull b) {
    ull d; asm("mul.rn.f32x2 %0, %1, %2;" : "=l"(d) : "l"(a), "l"(b)); return d;
}
__device__ __forceinline__ ull add2(ull a, ull b) {
    ull d; asm("add.rn.f32x2 %0, %1, %2;" : "=l"(d) : "l"(a), "l"(b)); return d;
}
__device__ __forceinline__ ull neg2(ull a) { return a ^ 0x8000000080000000ULL; }

__device__ __forceinline__ float softplus_f(float x) {
    return fmaxf(x, 0.0f) + log1pf(expf(-fabsf(x)));
}

// branchless packed complex pow: (rx,ry) = (bx,by)^e, e < 2048
__device__ __forceinline__ void cpow2(ull bx, ull by, unsigned e, ull& rx, ull& ry) {
    rx = pk2(1.0f, 1.0f); ry = pk2(0.0f, 0.0f);
    #pragma unroll
    for (int it = 0; it < 11; it++) {
        ull tx = fma2(rx, bx, neg2(mul2(ry, by)));
        ull ty = fma2(rx, by, mul2(ry, bx));
        bool m = (e & 1u) != 0u;
        rx = m ? tx : rx;
        ry = m ? ty : ry;
        e >>= 1;
        ull t2 = mul2(bx, by);
        bx = fma2(bx, bx, neg2(mul2(by, by)));
        by = add2(t2, t2);
    }
}

// ---------------- 0) pad W ----------------
__global__ void wprep_kernel(const float* __restrict__ W) {
    int idx = blockIdx.x * 256 + threadIdx.x;   // DM*128 = 65536
    int k = idx >> 7, c = idx & 127;
    g_Wp[idx] = (c < NC) ? W[k * NC + c] : 0.0f;
}

// ---------------- 1) fused LN + GEMM(split-K) + param transform ----------------
// 128 blocks x 256 threads. Block = 16 tokens.
// Warp w: tokg = w&1 (8 tokens), kq = w>>1 (K quarter of 128).
#define XROW 18
__global__ __launch_bounds__(256) void gemm_fused(
    const float* __restrict__ h, const float* __restrict__ mn,
    const float* __restrict__ lw, const float* __restrict__ lb,
    const float* __restrict__ bias)
{
    __shared__ __align__(16) float xsT[DM * XROW];   // 36.9 KB; reused as ps4 later

    int t  = threadIdx.x;
    int s0 = blockIdx.x * 16;

    // ---- LayerNorm: 16 threads per row, 16 rows; store TRANSPOSED ----
    {
        int r = t >> 4, sub = t & 15;
        const float4* h4 = (const float4*)h;
        float4 v[8];
        float sum = 0.f, sq = 0.f;
        #pragma unroll
        for (int q = 0; q < 8; q++) {
            v[q] = h4[(s0 + r) * (DM / 4) + sub + q * 16];
            sum += v[q].x + v[q].y + v[q].z + v[q].w;
            sq  += v[q].x * v[q].x + v[q].y * v[q].y + v[q].z * v[q].z + v[q].w * v[q].w;
        }
        #pragma unroll
        for (int o = 8; o; o >>= 1) {
            sum += __shfl_xor_sync(0xffffffffu, sum, o);
            sq  += __shfl_xor_sync(0xffffffffu, sq,  o);
        }
        float mu   = sum * (1.0f / DM);
        float var  = sq * (1.0f / DM) - mu * mu;
        float rstd = rsqrtf(var + 1e-5f);
        const float4* lw4 = (const float4*)lw;
        const float4* lb4 = (const float4*)lb;
        #pragma unroll
        for (int q = 0; q < 8; q++) {
            float4 wv = lw4[sub + q * 16], bv = lb4[sub + q * 16];
            int k0 = (sub + q * 16) * 4;
            xsT[(k0 + 0) * XROW + r] = (v[q].x - mu) * rstd * wv.x + bv.x;
            xsT[(k0 + 1) * XROW + r] = (v[q].y - mu) * rstd * wv.y + bv.y;
            xsT[(k0 + 2) * XROW + r] = (v[q].z - mu) * rstd * wv.z + bv.z;
            xsT[(k0 + 3) * XROW + r] = (v[q].w - mu) * rstd * wv.w + bv.w;
        }
    }
    __syncthreads();

    // ---- GEMM: warp = 8 tokens (4 pairs) x 128 cols, over its K quarter ----
    int lane = t & 31, w = t >> 5;
    int tokg = (w & 1) * 8, kq = w >> 1;
    ull A[4][4];
    #pragma unroll
    for (int p = 0; p < 4; p++)
        #pragma unroll
        for (int q = 0; q < 4; q++) A[p][q] = 0ULL;

    const float4* Wp4 = (const float4*)g_Wp;
    int kbeg = kq * 128, kend = kbeg + 128;
    #pragma unroll 4
    for (int k = kbeg; k < kend; k++) {
        ull x01 = *(const ull*)&xsT[k * XROW + tokg + 0];
        ull x23 = *(const ull*)&xsT[k * XROW + tokg + 2];
        ull x45 = *(const ull*)&xsT[k * XROW + tokg + 4];
        ull x67 = *(const ull*)&xsT[k * XROW + tokg + 6];
        float4 wv = Wp4[k * 32 + lane];
        ull wd0 = pk2(wv.x, wv.x), wd1 = pk2(wv.y, wv.y);
        ull wd2 = pk2(wv.z, wv.z), wd3 = pk2(wv.w, wv.w);
        A[0][0] = fma2(x01, wd0, A[0][0]); A[0][1] = fma2(x01, wd1, A[0][1]);
        A[0][2] = fma2(x01, wd2, A[0][2]); A[0][3] = fma2(x01, wd3, A[0][3]);
        A[1][0] = fma2(x23, wd0, A[1][0]); A[1][1] = fma2(x23, wd1, A[1][1]);
        A[1][2] = fma2(x23, wd2, A[1][2]); A[1][3] = fma2(x23, wd3, A[1][3]);
        A[2][0] = fma2(x45, wd0, A[2][0]); A[2][1] = fma2(x45, wd1, A[2][1]);
        A[2][2] = fma2(x45, wd2, A[2][2]); A[2][3] = fma2(x45, wd3, A[2][3]);
        A[3][0] = fma2(x67, wd0, A[3][0]); A[3][1] = fma2(x67, wd1, A[3][1]);
        A[3][2] = fma2(x67, wd2, A[3][2]); A[3][3] = fma2(x67, wd3, A[3][3]);
    }
    __syncthreads();   // x no longer needed; reuse xsT as ps4[4][16][128]

    // ---- write per-quarter partials ----
    float* ps4 = xsT;
    #pragma unroll
    for (int p = 0; p < 4; p++) {
        #pragma unroll
        for (int q = 0; q < 4; q++) {
            float e0, e1; upk2(A[p][q], e0, e1);
            int c = 4 * lane + q;
            int tok0 = tokg + 2 * p;
            ps4[(kq * 16 + tok0) * 128 + c]     = e0;
            ps4[(kq * 16 + tok0 + 1) * 128 + c] = e1;
        }
    }
    __syncthreads();

    // ---- sum 4 quarters into quarter 0 (ps[tok][c]) ----
    {
        float4* q0 = (float4*)ps4;
        #pragma unroll
        for (int j = 0; j < 2; j++) {
            int u4 = t * 2 + j;                 // 512 float4 slots = 16x128
            float4 a = q0[u4];
            float4 b = q0[512 + u4];
            float4 c = q0[1024 + u4];
            float4 d = q0[1536 + u4];
            a.x += b.x + c.x + d.x;
            a.y += b.y + c.y + d.y;
            a.z += b.z + c.z + d.z;
            a.w += b.w + c.w + d.w;
            q0[u4] = a;
        }
    }
    __syncthreads();

    // ---- param transform: 16 tokens x 13 imus x 2 channels = 416 units ----
    float* ps = ps4;
    for (int u = t; u < 16 * NI * 2; u += 256) {
        int r   = u / (2 * NI);
        int rem = u - r * 2 * NI;
        int i = rem >> 1, ch = rem & 1;
        int s = s0 + r;
        const float* P = ps + r * 128;
        int ck  = (ch ? 2 : 0) * NI + i;
        int cd  = (ch ? 3 : 1) * NI + i;
        int cc  = (ch ? 5 : 4) * NI + i;
        int cph = (ch ? 7 : 6) * NI + i;
        float pk  = P[ck]  + bias[ck];
        float pd  = P[cd]  + bias[cd];
        float pc  = P[cc]  + bias[cc];
        float pph = P[cph] + bias[cph];

        float d  = sqrtf(pd * pd + 1e-5f);
        float sp = softplus_f(pk);
        float kk = d * d * 0.25f + sp;
        float om = 0.5f * sqrtf(fmaxf(4.0f * kk - d * d, 0.0f));
        float dec = expf(-0.5f * d);
        float so, co; sincosf(om, &so, &co);
        float sph, cph_; sincosf(pph, &sph, &cph_);
        float4 v = make_float4(pc * cph_, pc * sph, dec * co, dec * so);
        if (ch) g_pang[i * S + s] = v;
        else {
            g_plin[i * S + s] = v;
            int c8 = 8 * NI + i;
            g_base[i * S + s] = mn[0] + P[c8] + bias[c8];
        }
    }
}

// ---------------- 2) triangular sweep: uniform 128x128 tiles, 4KB smem ----
template<bool DIAG>
__device__ __forceinline__ void run_tile(int a0, int b0, int i, float* pout,
                                         int lane, float* sbuf) {
    ull X[4], Y[4], CW[4], SW[4], NSW[4];
    ull X0[4], Y0[4];
    int aj[4];
    #pragma unroll
    for (int j = 0; j < 4; j++) {
        int a = a0 + j * 32 + lane;
        aj[j] = a;
        float4 pl = g_plin[i * S + a];
        float4 pa = g_pang[i * S + a];
        CW[j]  = pk2(pl.z, pa.z);
        SW[j]  = pk2(pl.w, pa.w);
        NSW[j] = neg2(SW[j]);
        ull x0 = pk2(pl.x, pa.x), y0 = pk2(pl.y, pa.y);
        if (DIAG) {
            X0[j] = x0; Y0[j] = y0;
            X[j] = 0ULL; Y[j] = 0ULL;
        } else {
            ull rx, ry;
            cpow2(CW[j], SW[j], (unsigned)(b0 - a), rx, ry);
            X[j] = fma2(x0, rx, neg2(mul2(y0, ry)));
            Y[j] = fma2(x0, ry, mul2(y0, rx));
        }
    }
    #pragma unroll 1
    for (int chunk = 0; chunk < 4; chunk++) {
        #pragma unroll 4
        for (int bb2 = 0; bb2 < 32; bb2++) {
            if (DIAG) {
                int b = b0 + chunk * 32 + bb2;
                #pragma unroll
                for (int j = 0; j < 4; j++) {
                    bool hit = (b == aj[j]);
                    X[j] = hit ? X0[j] : X[j];
                    Y[j] = hit ? Y0[j] : Y[j];
                }
            }
            ull s2 = add2(add2(Y[0], Y[1]), add2(Y[2], Y[3]));
            float slo, shi; upk2(s2, slo, shi);
            sbuf[bb2 * 32 + ((lane + bb2) & 31)] = slo + shi;
            #pragma unroll
            for (int j = 0; j < 4; j++) {
                ull t1 = mul2(Y[j], NSW[j]);
                ull t2 = mul2(X[j], SW[j]);
                X[j] = fma2(X[j], CW[j], t1);
                Y[j] = fma2(Y[j], CW[j], t2);
            }
        }
        __syncwarp();
        // fold: lane owns row bb2 == lane; rotated reads, 4-acc tree
        {
            const float* row = sbuf + lane * 32;
            float a0s = 0.f, a1s = 0.f, a2s = 0.f, a3s = 0.f;
            #pragma unroll
            for (int c = 0; c < 32; c += 4) {
                a0s += row[(lane + c + 0) & 31];
                a1s += row[(lane + c + 1) & 31];
                a2s += row[(lane + c + 2) & 31];
                a3s += row[(lane + c + 3) & 31];
            }
            pout[chunk * 32 + lane] = (a0s + a1s) + (a2s + a3s);
        }
        __syncwarp();
    }
}

// grid (136, 13): slot -> (ca, cb) triangular, ca <= cb
__global__ __launch_bounds__(32) void sweep_kernel() {
    __shared__ float sbuf[32 * 32];   // 4 KB
    int slot = blockIdx.x, i = blockIdx.y;
    int lane = threadIdx.x;
    int s = slot, cb = 0;
    while (s > cb) { s -= (cb + 1); cb++; }
    int ca = s;
    float* pout = g_partial + (ca * NI + i) * S + cb * 128;
    if (ca == cb) run_tile<true >(ca * 128, cb * 128, i, pout, lane, sbuf);
    else          run_tile<false>(ca * 128, cb * 128, i, pout, lane, sbuf);
}

// ---------------- 3) fold partials + base -> out (float4) ----------------
__global__ void reduce_kernel(float* __restrict__ out) {
    int idx4 = blockIdx.x * 256 + threadIdx.x;   // NI*S/4 = 6656
    if (idx4 >= NI * S / 4) return;
    int i  = idx4 / (S / 4);
    int b4 = idx4 & (S / 4 - 1);
    int cb = (b4 * 4) >> 7;
    const float4* base4 = (const float4*)g_base;
    float4 acc = base4[idx4];
    #pragma unroll
    for (int ca = 0; ca < 16; ca++) {
        if (ca <= cb) {
            float4 v = *(const float4*)&g_partial[(ca * NI + i) * S + b4 * 4];
            acc.x += v.x; acc.y += v.y; acc.z += v.z; acc.w += v.w;
        }
    }
    ((float4*)out)[idx4] = acc;
}

// ---------------- launch ----------------
extern "C" void kernel_launch(void* const* d_in, const int* in_sizes, int n_in,
                              void* d_out, int out_size) {
    const float* h    = (const float*)d_in[0];
    const float* mn   = (const float*)d_in[1];
    const float* lw   = (const float*)d_in[2];
    const float* lb   = (const float*)d_in[3];
    const float* W    = (const float*)d_in[4];
    const float* bias = (const float*)d_in[5];
    float* out = (float*)d_out;

    wprep_kernel<<<256, 256>>>(W);
    gemm_fused<<<S / 16, 256>>>(h, mn, lw, lb, bias);
    dim3 g(136, NI);
    sweep_kernel<<<g, 32>>>();
    reduce_kernel<<<(NI * S / 4 + 255) / 256, 256>>>(out);
}

// round 8
// speedup vs baseline: 1.4498x; 1.0225x over previous
#include <cuda_runtime.h>

#define S 2048
#define DM 512
#define NI 13
#define NC 117

typedef unsigned long long ull;

// ---------------- scratch ----------------
__device__ float  g_Wp[DM * 128];            // padded W, [k][128]
__device__ float4 g_plin[NI * S];            // {x0, y0, cw, sw} lin channel, [i][a]
__device__ float4 g_pang[NI * S];            // ang channel
__device__ float  g_base[NI * S];            // min + noise_bias, [i][b]
__device__ float  g_partial[16 * NI * S];    // [ca][i][b]
__device__ int    g_cnt[NI * 16];            // per-(i,cb) completion counters

// ---------------- packed f32x2 helpers ----------------
__device__ __forceinline__ ull pk2(float lo, float hi) {
    ull r; asm("mov.b64 %0, {%1,%2};" : "=l"(r) : "f"(lo), "f"(hi)); return r;
}
__device__ __forceinline__ void upk2(ull v, float& lo, float& hi) {
    asm("mov.b64 {%0,%1}, %2;" : "=f"(lo), "=f"(hi) : "l"(v));
}
__device__ __forceinline__ ull fma2(ull a, ull b, ull c) {
    ull d; asm("fma.rn.f32x2 %0, %1, %2, %3;" : "=l"(d) : "l"(a), "l"(b), "l"(c)); return d;
}
__device__ __forceinline__ ull mul2(ull a, ull b) {
    ull d; asm("mul.rn.f32x2 %0, %1, %2;" : "=l"(d) : "l"(a), "l"(b)); return d;
}
__device__ __forceinline__ ull add2(ull a, ull b) {
    ull d; asm("add.rn.f32x2 %0, %1, %2;" : "=l"(d) : "l"(a), "l"(b)); return d;
}
__device__ __forceinline__ ull neg2(ull a) { return a ^ 0x8000000080000000ULL; }

__device__ __forceinline__ float softplus_f(float x) {
    return fmaxf(x, 0.0f) + log1pf(expf(-fabsf(x)));
}

// branchless packed complex pow: (rx,ry) = (bx,by)^e, e < 2048
__device__ __forceinline__ void cpow2(ull bx, ull by, unsigned e, ull& rx, ull& ry) {
    rx = pk2(1.0f, 1.0f); ry = pk2(0.0f, 0.0f);
    #pragma unroll
    for (int it = 0; it < 11; it++) {
        ull tx = fma2(rx, bx, neg2(mul2(ry, by)));
        ull ty = fma2(rx, by, mul2(ry, bx));
        bool m = (e & 1u) != 0u;
        rx = m ? tx : rx;
        ry = m ? ty : ry;
        e >>= 1;
        ull t2 = mul2(bx, by);
        bx = fma2(bx, bx, neg2(mul2(by, by)));
        by = add2(t2, t2);
    }
}

// ---------------- 0) pad W + zero counters ----------------
__global__ void wprep_kernel(const float* __restrict__ W) {
    int idx = blockIdx.x * 256 + threadIdx.x;   // DM*128 = 65536
    int k = idx >> 7, c = idx & 127;
    g_Wp[idx] = (c < NC) ? W[k * NC + c] : 0.0f;
    if (idx < NI * 16) g_cnt[idx] = 0;
}

// ---------------- 1) fused LN + GEMM(split-K) + param transform ----------------
// 128 blocks x 256 threads. Block = 16 tokens.
// Warp w: tokg = w&1 (8 tokens), kq = w>>1 (K quarter of 128).
#define XROW 18
__global__ __launch_bounds__(256) void gemm_fused(
    const float* __restrict__ h, const float* __restrict__ mn,
    const float* __restrict__ lw, const float* __restrict__ lb,
    const float* __restrict__ bias)
{
    __shared__ __align__(16) float xsT[DM * XROW];   // 36.9 KB; reused as ps4 later

    int t  = threadIdx.x;
    int s0 = blockIdx.x * 16;

    // ---- LayerNorm: 16 threads per row, 16 rows; store TRANSPOSED ----
    {
        int r = t >> 4, sub = t & 15;
        const float4* h4 = (const float4*)h;
        float4 v[8];
        float sum = 0.f, sq = 0.f;
        #pragma unroll
        for (int q = 0; q < 8; q++) {
            v[q] = h4[(s0 + r) * (DM / 4) + sub + q * 16];
            sum += v[q].x + v[q].y + v[q].z + v[q].w;
            sq  += v[q].x * v[q].x + v[q].y * v[q].y + v[q].z * v[q].z + v[q].w * v[q].w;
        }
        #pragma unroll
        for (int o = 8; o; o >>= 1) {
            sum += __shfl_xor_sync(0xffffffffu, sum, o);
            sq  += __shfl_xor_sync(0xffffffffu, sq,  o);
        }
        float mu   = sum * (1.0f / DM);
        float var  = sq * (1.0f / DM) - mu * mu;
        float rstd = rsqrtf(var + 1e-5f);
        const float4* lw4 = (const float4*)lw;
        const float4* lb4 = (const float4*)lb;
        #pragma unroll
        for (int q = 0; q < 8; q++) {
            float4 wv = lw4[sub + q * 16], bv = lb4[sub + q * 16];
            int k0 = (sub + q * 16) * 4;
            xsT[(k0 + 0) * XROW + r] = (v[q].x - mu) * rstd * wv.x + bv.x;
            xsT[(k0 + 1) * XROW + r] = (v[q].y - mu) * rstd * wv.y + bv.y;
            xsT[(k0 + 2) * XROW + r] = (v[q].z - mu) * rstd * wv.z + bv.z;
            xsT[(k0 + 3) * XROW + r] = (v[q].w - mu) * rstd * wv.w + bv.w;
        }
    }
    __syncthreads();

    // ---- GEMM: warp = 8 tokens (4 pairs) x 128 cols, over its K quarter ----
    int lane = t & 31, w = t >> 5;
    int tokg = (w & 1) * 8, kq = w >> 1;
    ull A[4][4];
    #pragma unroll
    for (int p = 0; p < 4; p++)
        #pragma unroll
        for (int q = 0; q < 4; q++) A[p][q] = 0ULL;

    const float4* Wp4 = (const float4*)g_Wp;
    int kbeg = kq * 128, kend = kbeg + 128;
    #pragma unroll 8
    for (int k = kbeg; k < kend; k++) {
        ull x01 = *(const ull*)&xsT[k * XROW + tokg + 0];
        ull x23 = *(const ull*)&xsT[k * XROW + tokg + 2];
        ull x45 = *(const ull*)&xsT[k * XROW + tokg + 4];
        ull x67 = *(const ull*)&xsT[k * XROW + tokg + 6];
        float4 wv = Wp4[k * 32 + lane];
        ull wd0 = pk2(wv.x, wv.x), wd1 = pk2(wv.y, wv.y);
        ull wd2 = pk2(wv.z, wv.z), wd3 = pk2(wv.w, wv.w);
        A[0][0] = fma2(x01, wd0, A[0][0]); A[0][1] = fma2(x01, wd1, A[0][1]);
        A[0][2] = fma2(x01, wd2, A[0][2]); A[0][3] = fma2(x01, wd3, A[0][3]);
        A[1][0] = fma2(x23, wd0, A[1][0]); A[1][1] = fma2(x23, wd1, A[1][1]);
        A[1][2] = fma2(x23, wd2, A[1][2]); A[1][3] = fma2(x23, wd3, A[1][3]);
        A[2][0] = fma2(x45, wd0, A[2][0]); A[2][1] = fma2(x45, wd1, A[2][1]);
        A[2][2] = fma2(x45, wd2, A[2][2]); A[2][3] = fma2(x45, wd3, A[2][3]);
        A[3][0] = fma2(x67, wd0, A[3][0]); A[3][1] = fma2(x67, wd1, A[3][1]);
        A[3][2] = fma2(x67, wd2, A[3][2]); A[3][3] = fma2(x67, wd3, A[3][3]);
    }
    __syncthreads();   // x no longer needed; reuse xsT as ps4[4][16][128]

    // ---- write per-quarter partials ----
    float* ps4 = xsT;
    #pragma unroll
    for (int p = 0; p < 4; p++) {
        #pragma unroll
        for (int q = 0; q < 4; q++) {
            float e0, e1; upk2(A[p][q], e0, e1);
            int c = 4 * lane + q;
            int tok0 = tokg + 2 * p;
            ps4[(kq * 16 + tok0) * 128 + c]     = e0;
            ps4[(kq * 16 + tok0 + 1) * 128 + c] = e1;
        }
    }
    __syncthreads();

    // ---- sum 4 quarters into quarter 0 (ps[tok][c]) ----
    {
        float4* q0 = (float4*)ps4;
        #pragma unroll
        for (int j = 0; j < 2; j++) {
            int u4 = t * 2 + j;                 // 512 float4 slots = 16x128
            float4 a = q0[u4];
            float4 b = q0[512 + u4];
            float4 c = q0[1024 + u4];
            float4 d = q0[1536 + u4];
            a.x += b.x + c.x + d.x;
            a.y += b.y + c.y + d.y;
            a.z += b.z + c.z + d.z;
            a.w += b.w + c.w + d.w;
            q0[u4] = a;
        }
    }
    __syncthreads();

    // ---- param transform: 16 tokens x 13 imus x 2 channels = 416 units ----
    float* ps = ps4;
    for (int u = t; u < 16 * NI * 2; u += 256) {
        int r   = u / (2 * NI);
        int rem = u - r * 2 * NI;
        int i = rem >> 1, ch = rem & 1;
        int s = s0 + r;
        const float* P = ps + r * 128;
        int ck  = (ch ? 2 : 0) * NI + i;
        int cd  = (ch ? 3 : 1) * NI + i;
        int cc  = (ch ? 5 : 4) * NI + i;
        int cph = (ch ? 7 : 6) * NI + i;
        float pk  = P[ck]  + bias[ck];
        float pd  = P[cd]  + bias[cd];
        float pc  = P[cc]  + bias[cc];
        float pph = P[cph] + bias[cph];

        float d  = sqrtf(pd * pd + 1e-5f);
        float sp = softplus_f(pk);
        float kk = d * d * 0.25f + sp;
        float om = 0.5f * sqrtf(fmaxf(4.0f * kk - d * d, 0.0f));
        float dec = expf(-0.5f * d);
        float so, co; sincosf(om, &so, &co);
        float sph, cph_; sincosf(pph, &sph, &cph_);
        float4 v = make_float4(pc * cph_, pc * sph, dec * co, dec * so);
        if (ch) g_pang[i * S + s] = v;
        else {
            g_plin[i * S + s] = v;
            int c8 = 8 * NI + i;
            g_base[i * S + s] = mn[0] + P[c8] + bias[c8];
        }
    }
}

// ---------------- 2) triangular sweep + fused final fold ----------------
// smem: packed ull buffer, 32 b-slots x 32 lanes = 8 KB, rotation-indexed.

// steady tile: double-step (emit b and b+1 per iteration, rotate by w^2)
__device__ __forceinline__ void run_full(int a0, int b0, int i, float* pout,
                                         int lane, ull* sbuf) {
    ull X[4], Y[4], CW[4], SW[4], CW2[4], SW2[4], NSW2[4];
    #pragma unroll
    for (int j = 0; j < 4; j++) {
        int a = a0 + j * 32 + lane;
        float4 pl = g_plin[i * S + a];
        float4 pa = g_pang[i * S + a];
        CW[j] = pk2(pl.z, pa.z);
        SW[j] = pk2(pl.w, pa.w);
        // w^2
        ull t2 = mul2(CW[j], SW[j]);
        CW2[j]  = fma2(CW[j], CW[j], neg2(mul2(SW[j], SW[j])));
        SW2[j]  = add2(t2, t2);
        NSW2[j] = neg2(SW2[j]);
        ull rx, ry;
        cpow2(CW[j], SW[j], (unsigned)(b0 - a), rx, ry);
        ull x0 = pk2(pl.x, pa.x), y0 = pk2(pl.y, pa.y);
        X[j] = fma2(x0, rx, neg2(mul2(y0, ry)));
        Y[j] = fma2(x0, ry, mul2(y0, rx));
    }
    #pragma unroll 1
    for (int chunk = 0; chunk < 4; chunk++) {
        #pragma unroll 4
        for (int it = 0; it < 16; it++) {
            int bb0 = it * 2;
            // sum for b: tree of Y
            ull sA = add2(add2(Y[0], Y[1]), add2(Y[2], Y[3]));
            sbuf[bb0 * 32 + ((lane + bb0) & 31)] = sA;
            // sum for b+1: y' = x*sw + y*cw per group
            ull sB0 = fma2(X[0], SW[0], mul2(Y[0], CW[0]));
            ull sB1 = fma2(X[1], SW[1], mul2(Y[1], CW[1]));
            ull sB2 = fma2(X[2], SW[2], mul2(Y[2], CW[2]));
            ull sB3 = fma2(X[3], SW[3], mul2(Y[3], CW[3]));
            ull sB = add2(add2(sB0, sB1), add2(sB2, sB3));
            sbuf[(bb0 + 1) * 32 + ((lane + bb0 + 1) & 31)] = sB;
            // rotate by w^2
            #pragma unroll
            for (int j = 0; j < 4; j++) {
                ull t1 = mul2(Y[j], NSW2[j]);
                ull t2b = mul2(X[j], SW2[j]);
                X[j] = fma2(X[j], CW2[j], t1);
                Y[j] = fma2(Y[j], CW2[j], t2b);
            }
        }
        __syncwarp();
        // fold 32 b-slots: lane owns row bb == lane
        {
            const ull* row = sbuf + lane * 32;
            ull acc0 = 0ULL, acc1 = 0ULL;
            #pragma unroll
            for (int c = 0; c < 32; c += 2) {
                acc0 = add2(acc0, row[(lane + c + 0) & 31]);
                acc1 = add2(acc1, row[(lane + c + 1) & 31]);
            }
            ull acc = add2(acc0, acc1);
            float lo, hi; upk2(acc, lo, hi);
            pout[chunk * 32 + lane] = lo + hi;
        }
        __syncwarp();
    }
}

// diagonal tile: single-step with birth predicate
__device__ __forceinline__ void run_diag(int b0, int i, float* pout,
                                         int lane, ull* sbuf) {
    ull X[4], Y[4], CW[4], SW[4], NSW[4], X0[4], Y0[4];
    int aj[4];
    #pragma unroll
    for (int j = 0; j < 4; j++) {
        int a = b0 + j * 32 + lane;
        aj[j] = a;
        float4 pl = g_plin[i * S + a];
        float4 pa = g_pang[i * S + a];
        CW[j]  = pk2(pl.z, pa.z);
        SW[j]  = pk2(pl.w, pa.w);
        NSW[j] = neg2(SW[j]);
        X0[j] = pk2(pl.x, pa.x);
        Y0[j] = pk2(pl.y, pa.y);
        X[j] = 0ULL; Y[j] = 0ULL;
    }
    #pragma unroll 1
    for (int chunk = 0; chunk < 4; chunk++) {
        #pragma unroll 4
        for (int bb = 0; bb < 32; bb++) {
            int b = b0 + chunk * 32 + bb;
            #pragma unroll
            for (int j = 0; j < 4; j++) {
                bool hit = (b == aj[j]);
                X[j] = hit ? X0[j] : X[j];
                Y[j] = hit ? Y0[j] : Y[j];
            }
            ull s2 = add2(add2(Y[0], Y[1]), add2(Y[2], Y[3]));
            sbuf[bb * 32 + ((lane + bb) & 31)] = s2;
            #pragma unroll
            for (int j = 0; j < 4; j++) {
                ull t1 = mul2(Y[j], NSW[j]);
                ull t2 = mul2(X[j], SW[j]);
                X[j] = fma2(X[j], CW[j], t1);
                Y[j] = fma2(Y[j], CW[j], t2);
            }
        }
        __syncwarp();
        {
            const ull* row = sbuf + lane * 32;
            ull acc0 = 0ULL, acc1 = 0ULL;
            #pragma unroll
            for (int c = 0; c < 32; c += 2) {
                acc0 = add2(acc0, row[(lane + c + 0) & 31]);
                acc1 = add2(acc1, row[(lane + c + 1) & 31]);
            }
            ull acc = add2(acc0, acc1);
            float lo, hi; upk2(acc, lo, hi);
            pout[chunk * 32 + lane] = lo + hi;
        }
        __syncwarp();
    }
}

// grid (136, 13): slot -> (ca, cb) triangular, ca <= cb. Last tile of a
// (i, cb) column folds base + all partials into out (deterministic order).
__global__ __launch_bounds__(32) void sweep_kernel(float* __restrict__ out) {
    __shared__ ull sbuf[32 * 32];   // 8 KB
    int slot = blockIdx.x, i = blockIdx.y;
    int lane = threadIdx.x;
    int s = slot, cb = 0;
    while (s > cb) { s -= (cb + 1); cb++; }
    int ca = s;
    float* pout = g_partial + (ca * NI + i) * S + cb * 128;
    if (ca == cb) run_diag(cb * 128, i, pout, lane, sbuf);
    else          run_full(ca * 128, cb * 128, i, pout, lane, sbuf);

    // fused fold: last tile of this (i, cb) column writes the output
    __threadfence();
    int last = 0;
    if (lane == 0)
        last = (atomicAdd(&g_cnt[i * 16 + cb], 1) == cb);
    last = __shfl_sync(0xffffffffu, last, 0);
    if (last) {
        __threadfence();
        #pragma unroll
        for (int g = 0; g < 4; g++) {
            int b = cb * 128 + g * 32 + lane;
            float acc = g_base[i * S + b];
            #pragma unroll
            for (int c2 = 0; c2 < 16; c2++)
                if (c2 <= cb) acc += g_partial[(c2 * NI + i) * S + b];
            out[i * S + b] = acc;
        }
    }
}

// ---------------- launch ----------------
extern "C" void kernel_launch(void* const* d_in, const int* in_sizes, int n_in,
                              void* d_out, int out_size) {
    const float* h    = (const float*)d_in[0];
    const float* mn   = (const float*)d_in[1];
    const float* lw   = (const float*)d_in[2];
    const float* lb   = (const float*)d_in[3];
    const float* W    = (const float*)d_in[4];
    const float* bias = (const float*)d_in[5];
    float* out = (float*)d_out;

    wprep_kernel<<<256, 256>>>(W);
    gemm_fused<<<S / 16, 256>>>(h, mn, lw, lb, bias);
    dim3 g(136, NI);
    sweep_kernel<<<g, 32>>>(out);
}